// round 1
// baseline (speedup 1.0000x reference)
#include <cuda_runtime.h>
#include <math.h>
#include <math_constants.h>

#define C_CLASSES 1000
#define NBLK 512
#define THREADS 256
#define WPB (THREADS / 32)

__device__ float g_mlist1[C_CLASSES];
__device__ float g_partials[NBLK];

// ---------------------------------------------------------------------------
// Kernel 1: compute m_list1 from cls_num_list / class_difficulty / epoch.
// One block, 1024 threads (C=1000).
// ---------------------------------------------------------------------------
__global__ void prep_kernel(const float* __restrict__ cls,
                            const float* __restrict__ diff,
                            const int* __restrict__ epoch_p,
                            int nC) {
    __shared__ float s_min[32], s_sum[32], s_max[32];
    int tid = threadIdx.x;

    float c  = (tid < nC) ? cls[tid] : CUDART_INF_F;
    float cs = (tid < nC) ? c : 0.0f;
    float d  = (tid < nC) ? diff[tid] : 0.0f;
    float w  = 0.5f * d * d + 0.3f;               // ALPHA*d^P + BETA
    float wm = (tid < nC) ? w : -CUDART_INF_F;

    float mn = c, sm = cs, mx = wm;
    #pragma unroll
    for (int o = 16; o; o >>= 1) {
        mn = fminf(mn, __shfl_xor_sync(0xffffffffu, mn, o));
        sm += __shfl_xor_sync(0xffffffffu, sm, o);
        mx = fmaxf(mx, __shfl_xor_sync(0xffffffffu, mx, o));
    }
    int wid = tid >> 5, lane = tid & 31;
    if (lane == 0) { s_min[wid] = mn; s_sum[wid] = sm; s_max[wid] = mx; }
    __syncthreads();
    if (wid == 0) {
        int nw = (blockDim.x + 31) >> 5;
        mn = (lane < nw) ? s_min[lane] : CUDART_INF_F;
        sm = (lane < nw) ? s_sum[lane] : 0.0f;
        mx = (lane < nw) ? s_max[lane] : -CUDART_INF_F;
        #pragma unroll
        for (int o = 16; o; o >>= 1) {
            mn = fminf(mn, __shfl_xor_sync(0xffffffffu, mn, o));
            sm += __shfl_xor_sync(0xffffffffu, sm, o);
            mx = fmaxf(mx, __shfl_xor_sync(0xffffffffu, mx, o));
        }
        if (lane == 0) { s_min[0] = mn; s_sum[0] = sm; s_max[0] = mx; }
    }
    __syncthreads();
    float min_c = s_min[0], sum_c = s_sum[0], wmax = s_max[0];
    float max_m = -logf(min_c / sum_c) - 0.165745444183859f;

    if (tid < nC) {
        // m_list = max_m * (1/sqrt(cls)) / (1/sqrt(min)) = max_m * sqrt(min/cls)
        float m_l = max_m * sqrtf(min_c / cls[tid]);
        int epoch = epoch_p ? *epoch_p : 70;
        float ml1 = m_l;
        if (epoch >= 60) {
            float ee = (epoch >= 80) ? 1.0f : (float)(epoch - 60) / 20.0f;
            float wsc = w * (max_m / wmax);        // weights scaled
            ml1 = m_l + wsc * ee * 0.5f;
        }
        g_mlist1[tid] = ml1;
    }
}

// ---------------------------------------------------------------------------
// Kernel 2: per-row online logsumexp with margin applied at the target logit.
// One warp per row; persistent grid. Deterministic partials (no atomics).
// ---------------------------------------------------------------------------
__global__ void __launch_bounds__(THREADS, 4)
loss_kernel(const float* __restrict__ x,
            const int* __restrict__ targets,
            int nB) {
    const int lane = threadIdx.x & 31;
    const int warp = blockIdx.x * WPB + (threadIdx.x >> 5);
    const int total_warps = gridDim.x * WPB;
    const int NVEC = C_CLASSES / 4;   // 250 float4 per row

    float acc = 0.0f;

    for (int row = warp; row < nB; row += total_warps) {
        const int t = targets[row];           // broadcast within warp (same addr)
        const float margin = g_mlist1[t];
        const float4* xr = reinterpret_cast<const float4*>(x + (size_t)row * C_CLASSES);

        float m = -CUDART_INF_F;
        float s = 0.0f;
        float tval = -CUDART_INF_F;

        for (int i = lane; i < NVEC; i += 32) {
            float4 v = __ldg(&xr[i]);
            unsigned r = (unsigned)(t - i * 4);
            if (r < 4u) {                     // target logit lives in this float4
                float* pv = &v.x;
                pv[r] -= margin;
                tval = pv[r];
            }
            float lm = fmaxf(fmaxf(v.x, v.y), fmaxf(v.z, v.w));
            float nm = fmaxf(m, lm);
            s = s * __expf(m - nm)
              + __expf(v.x - nm) + __expf(v.y - nm)
              + __expf(v.z - nm) + __expf(v.w - nm);
            m = nm;
        }

        // warp merge of (m, s) and broadcast of tval
        #pragma unroll
        for (int o = 16; o; o >>= 1) {
            float om = __shfl_xor_sync(0xffffffffu, m, o);
            float os = __shfl_xor_sync(0xffffffffu, s, o);
            float nm = fmaxf(m, om);
            s = s * __expf(m - nm) + os * __expf(om - nm);
            m = nm;
            tval = fmaxf(tval, __shfl_xor_sync(0xffffffffu, tval, o));
        }

        // -log_softmax at target = logsumexp - adjusted_target_logit
        acc += (m + logf(s)) - tval;
    }

    __shared__ float sacc[WPB];
    if (lane == 0) sacc[threadIdx.x >> 5] = acc;
    __syncthreads();
    if (threadIdx.x == 0) {
        float tot = 0.0f;
        #pragma unroll
        for (int i = 0; i < WPB; i++) tot += sacc[i];
        g_partials[blockIdx.x] = tot;
    }
}

// ---------------------------------------------------------------------------
// Kernel 3: reduce NBLK partials, write mean loss.
// ---------------------------------------------------------------------------
__global__ void finalize_kernel(float* __restrict__ out, int nB) {
    __shared__ float sh[NBLK / 32];
    int tid = threadIdx.x;   // NBLK threads
    float v = g_partials[tid];
    #pragma unroll
    for (int o = 16; o; o >>= 1) v += __shfl_xor_sync(0xffffffffu, v, o);
    if ((tid & 31) == 0) sh[tid >> 5] = v;
    __syncthreads();
    if (tid < 32) {
        v = (tid < NBLK / 32) ? sh[tid] : 0.0f;
        #pragma unroll
        for (int o = 16; o; o >>= 1) v += __shfl_xor_sync(0xffffffffu, v, o);
        if (tid == 0) out[0] = v / (float)nB;
    }
}

// ---------------------------------------------------------------------------
extern "C" void kernel_launch(void* const* d_in, const int* in_sizes, int n_in,
                              void* d_out, int out_size) {
    const float* x       = (const float*)d_in[0];
    const int*   targets = (const int*)  d_in[1];
    const float* cls     = (const float*)d_in[2];
    const float* diff    = (const float*)d_in[3];
    const int*   epoch   = (n_in >= 5) ? (const int*)d_in[4] : nullptr;

    int nB = in_sizes[1];          // targets length = batch
    int nC = in_sizes[2];          // classes (1000)
    float* out = (float*)d_out;

    prep_kernel<<<1, 1024>>>(cls, diff, epoch, nC);
    loss_kernel<<<NBLK, THREADS>>>(x, targets, nB);
    finalize_kernel<<<1, NBLK>>>(out, nB);
}

// round 4
// speedup vs baseline: 1.3934x; 1.3934x over previous
#include <cuda_runtime.h>
#include <math.h>
#include <math_constants.h>

#define C_CLASSES 1000
#define NVEC      (C_CLASSES / 4)   // 250 float4 per row
#define THREADS   256
#define WPB       (THREADS / 32)
#define NBLK      592               // 4 blocks/SM * 148 SMs
#define MAGIC     0.165745444183859f

__device__ float g_partials[NBLK];

// ---------------------------------------------------------------------------
// Main kernel: fused scalar prep + per-row logsumexp with margin at target.
// Writes one deterministic partial per block. No cross-block sync.
// ---------------------------------------------------------------------------
__global__ void __launch_bounds__(THREADS, 4)
fused_loss_kernel(const float* __restrict__ x,
                  const int*   __restrict__ targets,
                  const float* __restrict__ cls,
                  const float* __restrict__ diff,
                  const int*   __restrict__ epoch_p,
                  int nB, int nC)
{
    const int tid  = threadIdx.x;
    const int lane = tid & 31;
    const int wid  = tid >> 5;

    // ---- Phase 0: per-block redundant scalar prep (~1000 elems, L2-hot) ---
    __shared__ float s_mn[WPB], s_sm[WPB], s_mx[WPB];
    __shared__ float s_scalars[3];

    {
        float mn = CUDART_INF_F, sm = 0.0f, mx = -CUDART_INF_F;
        for (int i = tid; i < nC; i += THREADS) {
            float c = __ldg(cls + i);
            float d = __ldg(diff + i);
            mn = fminf(mn, c);
            sm += c;
            mx = fmaxf(mx, 0.5f * d * d + 0.3f);
        }
        #pragma unroll
        for (int o = 16; o; o >>= 1) {
            mn = fminf(mn, __shfl_xor_sync(0xffffffffu, mn, o));
            sm += __shfl_xor_sync(0xffffffffu, sm, o);
            mx = fmaxf(mx, __shfl_xor_sync(0xffffffffu, mx, o));
        }
        if (lane == 0) { s_mn[wid] = mn; s_sm[wid] = sm; s_mx[wid] = mx; }
        __syncthreads();
        if (tid == 0) {
            mn = s_mn[0]; sm = s_sm[0]; mx = s_mx[0];
            #pragma unroll
            for (int i = 1; i < WPB; i++) {
                mn = fminf(mn, s_mn[i]);
                sm += s_sm[i];
                mx = fmaxf(mx, s_mx[i]);
            }
            s_scalars[0] = mn; s_scalars[1] = sm; s_scalars[2] = mx;
        }
        __syncthreads();
    }

    const float min_c = s_scalars[0];
    const float sum_c = s_scalars[1];
    const float wmax  = s_scalars[2];
    const float max_m = -logf(min_c / sum_c) - MAGIC;

    const int epoch = epoch_p ? __ldg(epoch_p) : 70;
    float ee = 0.0f;
    if (epoch >= 60) ee = (epoch >= 80) ? 1.0f : (float)(epoch - 60) * (1.0f / 20.0f);
    const float wscale = ee * 0.5f * max_m / wmax;   // multiplies (0.5 d^2 + 0.3)

    // ---- Phase 1: stream rows ---------------------------------------------
    const int gwarp = blockIdx.x * WPB + wid;
    const int totw  = gridDim.x * WPB;

    float acc = 0.0f;

    for (int row = gwarp; row < nB; row += totw) {
        const int t = __ldg(targets + row);
        const float4* xr = reinterpret_cast<const float4*>(x + (size_t)row * C_CLASSES);

        // Front-batched loads: lane handles vec indices lane + 32*j, j=0..7.
        float4 v[8];
        #pragma unroll
        for (int j = 0; j < 7; j++)
            v[j] = __ldg(xr + lane + 32 * j);
        {
            int idx = lane + 224;
            if (idx < NVEC) v[7] = __ldg(xr + idx);
            else            v[7] = make_float4(-1e30f, -1e30f, -1e30f, -1e30f);
        }

        // Extract raw target logit (SEL chain, no dynamic indexing).
        float xt = -CUDART_INF_F;
        #pragma unroll
        for (int j = 0; j < 8; j++) {
            unsigned r = (unsigned)(t - (lane + 32 * j) * 4);
            if (r < 4u) {
                float e = (r == 0) ? v[j].x : (r == 1) ? v[j].y
                        : (r == 2) ? v[j].z : v[j].w;
                xt = e;
            }
        }

        // Row max (no exp in the dependency chain).
        float m = -CUDART_INF_F;
        #pragma unroll
        for (int j = 0; j < 8; j++)
            m = fmaxf(m, fmaxf(fmaxf(v[j].x, v[j].y), fmaxf(v[j].z, v[j].w)));
        #pragma unroll
        for (int o = 16; o; o >>= 1) {
            m  = fmaxf(m,  __shfl_xor_sync(0xffffffffu, m,  o));
            xt = fmaxf(xt, __shfl_xor_sync(0xffffffffu, xt, o));
        }

        // Independent exps, single pass.
        float s = 0.0f;
        #pragma unroll
        for (int j = 0; j < 8; j++) {
            s += __expf(v[j].x - m) + __expf(v[j].y - m)
               + __expf(v[j].z - m) + __expf(v[j].w - m);
        }
        #pragma unroll
        for (int o = 16; o; o >>= 1)
            s += __shfl_xor_sync(0xffffffffu, s, o);

        // Margin correction (post-hoc, warp-uniform).
        const float ct = __ldg(cls + t);
        const float dt = __ldg(diff + t);
        const float margin = max_m * sqrtf(min_c / ct)
                           + (0.5f * dt * dt + 0.3f) * wscale;
        const float xta  = xt - margin;
        const float sadj = s - __expf(xt - m) + __expf(xta - m);
        acc += (m + logf(sadj)) - xta;
    }

    // ---- Phase 2: block partial (deterministic, no atomics) ---------------
    __shared__ float sacc[WPB];
    if (lane == 0) sacc[wid] = acc;
    __syncthreads();
    if (tid == 0) {
        float tot = 0.0f;
        #pragma unroll
        for (int i = 0; i < WPB; i++) tot += sacc[i];
        g_partials[blockIdx.x] = tot;
    }
}

// ---------------------------------------------------------------------------
// Finalize: reduce NBLK partials -> mean loss. One block.
// ---------------------------------------------------------------------------
__global__ void finalize_kernel(float* __restrict__ out, int nB) {
    __shared__ float sh[THREADS / 32];
    int tid = threadIdx.x;
    float v = 0.0f;
    for (int i = tid; i < NBLK; i += THREADS)
        v += g_partials[i];
    #pragma unroll
    for (int o = 16; o; o >>= 1)
        v += __shfl_xor_sync(0xffffffffu, v, o);
    if ((tid & 31) == 0) sh[tid >> 5] = v;
    __syncthreads();
    if (tid < 32) {
        v = (tid < THREADS / 32) ? sh[tid] : 0.0f;
        #pragma unroll
        for (int o = 16; o; o >>= 1)
            v += __shfl_xor_sync(0xffffffffu, v, o);
        if (tid == 0) out[0] = v / (float)nB;
    }
}

// ---------------------------------------------------------------------------
extern "C" void kernel_launch(void* const* d_in, const int* in_sizes, int n_in,
                              void* d_out, int out_size) {
    const float* x       = (const float*)d_in[0];
    const int*   targets = (const int*)  d_in[1];
    const float* cls     = (const float*)d_in[2];
    const float* diff    = (const float*)d_in[3];
    const int*   epoch   = (n_in >= 5) ? (const int*)d_in[4] : nullptr;

    int nB = in_sizes[1];
    int nC = in_sizes[2];
    float* out = (float*)d_out;

    fused_loss_kernel<<<NBLK, THREADS>>>(x, targets, cls, diff, epoch, nB, nC);
    finalize_kernel<<<1, THREADS>>>(out, nB);
}

// round 5
// speedup vs baseline: 1.4137x; 1.0146x over previous
#include <cuda_runtime.h>
#include <math.h>
#include <math_constants.h>

#define C_CLASSES 1000
#define NVEC      (C_CLASSES / 4)   // 250 float4 per row
#define THREADS   256
#define WPB       (THREADS / 32)
#define NBLK      592               // 4 blocks/SM * 148 SMs
#define MAGIC     0.165745444183859f

__device__ float    g_partials[NBLK];
__device__ unsigned g_count = 0;

__global__ void __launch_bounds__(THREADS, 4)
fused_loss_kernel(const float* __restrict__ x,
                  const int*   __restrict__ targets,
                  const float* __restrict__ cls,
                  const float* __restrict__ diff,
                  const int*   __restrict__ epoch_p,
                  int nB, int nC,
                  float* __restrict__ out)
{
    const int tid  = threadIdx.x;
    const int lane = tid & 31;
    const int wid  = tid >> 5;

    const int gwarp = blockIdx.x * WPB + wid;
    const int totw  = gridDim.x * WPB;

    // ---- Prefetch first row BEFORE the prep barrier (hides prep latency) --
    int    row  = gwarp;
    bool   have = (row < nB);
    int    t    = 0;
    float4 v[8];
    if (have) {
        t = __ldg(targets + row);
        const float4* xr = reinterpret_cast<const float4*>(x + (size_t)row * C_CLASSES);
        #pragma unroll
        for (int j = 0; j < 7; j++)
            v[j] = __ldg(xr + lane + 32 * j);
        int idx = lane + 224;
        if (idx < NVEC) v[7] = __ldg(xr + idx);
        else            v[7] = make_float4(-1e30f, -1e30f, -1e30f, -1e30f);
    }

    // ---- Phase 0: per-block redundant scalar prep (L2-hot, ~1000 elems) ---
    __shared__ float s_mn[WPB], s_sm[WPB], s_mx[WPB];
    __shared__ float s_scalars[3];

    {
        float mn = CUDART_INF_F, sm = 0.0f, mx = -CUDART_INF_F;
        for (int i = tid; i < nC; i += THREADS) {
            float c = __ldg(cls + i);
            float d = __ldg(diff + i);
            mn = fminf(mn, c);
            sm += c;
            mx = fmaxf(mx, 0.5f * d * d + 0.3f);
        }
        #pragma unroll
        for (int o = 16; o; o >>= 1) {
            mn = fminf(mn, __shfl_xor_sync(0xffffffffu, mn, o));
            sm += __shfl_xor_sync(0xffffffffu, sm, o);
            mx = fmaxf(mx, __shfl_xor_sync(0xffffffffu, mx, o));
        }
        if (lane == 0) { s_mn[wid] = mn; s_sm[wid] = sm; s_mx[wid] = mx; }
        __syncthreads();
        if (tid == 0) {
            mn = s_mn[0]; sm = s_sm[0]; mx = s_mx[0];
            #pragma unroll
            for (int i = 1; i < WPB; i++) {
                mn = fminf(mn, s_mn[i]);
                sm += s_sm[i];
                mx = fmaxf(mx, s_mx[i]);
            }
            s_scalars[0] = mn; s_scalars[1] = sm; s_scalars[2] = mx;
        }
        __syncthreads();
    }

    const float min_c = s_scalars[0];
    const float sum_c = s_scalars[1];
    const float wmax  = s_scalars[2];
    const float max_m = -logf(min_c / sum_c) - MAGIC;

    const int epoch = epoch_p ? __ldg(epoch_p) : 70;
    float ee = 0.0f;
    if (epoch >= 60) ee = (epoch >= 80) ? 1.0f : (float)(epoch - 60) * (1.0f / 20.0f);
    const float wscale = ee * 0.5f * max_m / wmax;   // multiplies (0.5 d^2 + 0.3)

    // ---- Phase 1: stream rows (loads prefetched at loop bottom) -----------
    float acc = 0.0f;

    while (have) {
        // Extract raw target logit (SEL chain, no dynamic indexing).
        float xt = -CUDART_INF_F;
        #pragma unroll
        for (int j = 0; j < 8; j++) {
            unsigned r = (unsigned)(t - (lane + 32 * j) * 4);
            if (r < 4u) {
                float e = (r == 0) ? v[j].x : (r == 1) ? v[j].y
                        : (r == 2) ? v[j].z : v[j].w;
                xt = e;
            }
        }

        // Row max (no exp in the dependency chain).
        float m = -CUDART_INF_F;
        #pragma unroll
        for (int j = 0; j < 8; j++)
            m = fmaxf(m, fmaxf(fmaxf(v[j].x, v[j].y), fmaxf(v[j].z, v[j].w)));
        #pragma unroll
        for (int o = 16; o; o >>= 1) {
            m  = fmaxf(m,  __shfl_xor_sync(0xffffffffu, m,  o));
            xt = fmaxf(xt, __shfl_xor_sync(0xffffffffu, xt, o));
        }

        // Independent exps, single pass.
        float s = 0.0f;
        #pragma unroll
        for (int j = 0; j < 8; j++) {
            s += __expf(v[j].x - m) + __expf(v[j].y - m)
               + __expf(v[j].z - m) + __expf(v[j].w - m);
        }
        #pragma unroll
        for (int o = 16; o; o >>= 1)
            s += __shfl_xor_sync(0xffffffffu, s, o);

        // Margin correction (post-hoc, warp-uniform). Uses current t.
        const float ct = __ldg(cls + t);
        const float dt = __ldg(diff + t);
        const float margin = max_m * sqrtf(min_c / ct)
                           + (0.5f * dt * dt + 0.3f) * wscale;
        const float xta  = xt - margin;
        const float sadj = s - __expf(xt - m) + __expf(xta - m);
        acc += (m + logf(sadj)) - xta;

        // Prefetch next row.
        row += totw;
        have = (row < nB);
        if (have) {
            t = __ldg(targets + row);
            const float4* xr = reinterpret_cast<const float4*>(x + (size_t)row * C_CLASSES);
            #pragma unroll
            for (int j = 0; j < 7; j++)
                v[j] = __ldg(xr + lane + 32 * j);
            int idx = lane + 224;
            if (idx < NVEC) v[7] = __ldg(xr + idx);
            else            v[7] = make_float4(-1e30f, -1e30f, -1e30f, -1e30f);
        }
    }

    // ---- Phase 2: block partial + ticketed last-block final reduce --------
    __shared__ float sacc[WPB];
    __shared__ float s_final[WPB];
    __shared__ int   s_last;
    if (lane == 0) sacc[wid] = acc;
    __syncthreads();

    if (tid == 0) {
        float tot = 0.0f;
        #pragma unroll
        for (int i = 0; i < WPB; i++) tot += sacc[i];
        g_partials[blockIdx.x] = tot;
        __threadfence();
        unsigned tk = atomicAdd(&g_count, 1u);
        s_last = (tk == gridDim.x - 1) ? 1 : 0;
    }
    __syncthreads();

    if (s_last) {
        float vv = 0.0f;
        for (int i = tid; i < gridDim.x; i += THREADS)
            vv += g_partials[i];
        #pragma unroll
        for (int o = 16; o; o >>= 1)
            vv += __shfl_xor_sync(0xffffffffu, vv, o);
        if (lane == 0) s_final[wid] = vv;
        __syncthreads();
        if (tid == 0) {
            float tot = 0.0f;
            #pragma unroll
            for (int i = 0; i < WPB; i++) tot += s_final[i];
            out[0] = tot / (float)nB;
            g_count = 0;                // self-reset for next graph replay
        }
    }
}

extern "C" void kernel_launch(void* const* d_in, const int* in_sizes, int n_in,
                              void* d_out, int out_size) {
    const float* x       = (const float*)d_in[0];
    const int*   targets = (const int*)  d_in[1];
    const float* cls     = (const float*)d_in[2];
    const float* diff    = (const float*)d_in[3];
    const int*   epoch   = (n_in >= 5) ? (const int*)d_in[4] : nullptr;

    int nB = in_sizes[1];
    int nC = in_sizes[2];
    float* out = (float*)d_out;

    fused_loss_kernel<<<NBLK, THREADS>>>(x, targets, cls, diff, epoch,
                                         nB, nC, out);
}